// round 16
// baseline (speedup 1.0000x reference)
#include <cuda_runtime.h>
#include <cuda_fp16.h>
#include <cstdint>

#define BATCH  16384
#define D      512
#define OUTD   2048
#define NLAYER 4

#define BM 128
#define BN 128
#define NKT 8                             // k-tiles of 64 halves
#define NROWB (BATCH / BM)                // 128
#define NITEMS (NLAYER * NROWB * 4)       // 2048
#define STAGE_BYTES (BM * 128 + BN * 128) // 32768
#define SMEM_MAIN (3 * STAGE_BYTES)       // 98304
#define SMEM_TOTAL (SMEM_MAIN + 2048)

__device__ __align__(16) float  g_wsum[NLAYER * D];
__device__ __align__(16) float  g_dot[3][3][BATCH];
__device__ __align__(16) float  g_sum[3][BATCH];
__device__ __align__(16) unsigned g_ready[3][NROWB];
__device__ unsigned g_ticket;
__device__ __half g_ha[4][(size_t)BATCH * D];
__device__ __half g_wh[(size_t)NLAYER * D * D];

// ---------------- helpers ----------------
__device__ __forceinline__ uint32_t s2u(const void* p) {
    uint32_t a;
    asm("{ .reg .u64 t; cvta.to.shared.u64 t, %1; cvt.u32.u64 %0, t; }" : "=r"(a) : "l"(p));
    return a;
}
__device__ __forceinline__ uint64_t g2g(const void* p) {
    uint64_t a;
    asm("cvta.to.global.u64 %0, %1;" : "=l"(a) : "l"(p));
    return a;
}
__device__ __forceinline__ void cp16(uint32_t s, uint64_t g) {
    asm volatile("cp.async.cg.shared.global [%0], [%1], 16;" :: "r"(s), "l"(g) : "memory");
}
#define MBAR_INIT(a, n) asm volatile("mbarrier.init.shared.b64 [%0], %1;" :: "r"(a), "r"(n) : "memory")
#define MBAR_ARRIVE(a)  asm volatile("mbarrier.arrive.shared.b64 _, [%0];" :: "r"(a) : "memory")
#define CP_MBAR_ARRIVE(a) \
    asm volatile("cp.async.mbarrier.arrive.noinc.shared.b64 [%0];" :: "r"(a) : "memory")
#define MBAR_WAIT(a, par) do {                                                        \
    uint32_t _m = (a), _p = (par), _d;                                                \
    asm volatile("{ .reg .pred p; mbarrier.try_wait.parity.acquire.cta.shared::cta.b64 p, [%1], %2; selp.b32 %0,1,0,p; }" \
                 : "=r"(_d) : "r"(_m), "r"(_p) : "memory");                           \
    if (!_d) {                                                                        \
        asm volatile("{ .reg .pred P1; WL_%=: mbarrier.try_wait.parity.acquire.cta.shared::cta.b64 P1, [%0], %1, 0x989680; @P1 bra.uni WD_%=; bra.uni WL_%=; WD_%=: }" \
                     :: "r"(_m), "r"(_p) : "memory");                                 \
    } } while (0)

__device__ __forceinline__ void ldsm4(uint32_t& r0, uint32_t& r1, uint32_t& r2, uint32_t& r3,
                                      uint32_t addr) {
    asm volatile("ldmatrix.sync.aligned.m8n8.x4.shared.b16 {%0,%1,%2,%3}, [%4];"
                 : "=r"(r0), "=r"(r1), "=r"(r2), "=r"(r3) : "r"(addr));
}
__device__ __forceinline__ void mma_f16(float* c, const uint32_t* a, const uint32_t* b) {
    asm volatile(
        "mma.sync.aligned.m16n8k16.row.col.f32.f16.f16.f32 "
        "{%0,%1,%2,%3}, {%4,%5,%6,%7}, {%8,%9}, {%0,%1,%2,%3};\n"
        : "+f"(c[0]), "+f"(c[1]), "+f"(c[2]), "+f"(c[3])
        : "r"(a[0]), "r"(a[1]), "r"(a[2]), "r"(a[3]), "r"(b[0]), "r"(b[1]));
}

// ---------------- fused prep ----------------
#define PREP_CONV_BLKS 2048
#define PREP_W_BLKS    256
#define PREP_ZERO_BLKS 180
#define PREP_BLKS (PREP_CONV_BLKS + PREP_W_BLKS + PREP_ZERO_BLKS)

__global__ void prep_all(const float* __restrict__ x, const float* __restrict__ W) {
    int b = blockIdx.x;
    int warp = threadIdx.x >> 5, lane = threadIdx.x & 31;

    if (b < PREP_CONV_BLKS) {
        int row = b * 8 + warp;
        const float4* rp = (const float4*)(x + (size_t)row * D);
        __half* hp = g_ha[0] + (size_t)row * D;
        float s = 0.f;
#pragma unroll
        for (int k = 0; k < 4; k++) {
            int i4 = lane + 32 * k;
            float4 v = rp[i4];
            s += v.x + v.y + v.z + v.w;
            __half2 h01 = __floats2half2_rn(v.x, v.y);
            __half2 h23 = __floats2half2_rn(v.z, v.w);
            uint2 pk = make_uint2(*(uint32_t*)&h01, *(uint32_t*)&h23);
            *(uint2*)(hp + i4 * 4) = pk;
        }
#pragma unroll
        for (int off = 16; off; off >>= 1) s += __shfl_xor_sync(0xffffffffu, s, off);
        if (lane == 0) g_sum[0][row] = s;
    } else if (b < PREP_CONV_BLKS + PREP_W_BLKS) {
        int wrow = (b - PREP_CONV_BLKS) * 8 + warp;
        const float4* row = (const float4*)(W + (size_t)wrow * D);
        __half* hrow = g_wh + (size_t)wrow * D;
        float s = 0.f;
#pragma unroll
        for (int k = 0; k < 4; k++) {
            int i4 = lane + 32 * k;
            float4 v = row[i4];
            s += v.x + v.y + v.z + v.w;
            __half2 h01 = __floats2half2_rn(v.x, v.y);
            __half2 h23 = __floats2half2_rn(v.z, v.w);
            uint2 pk = make_uint2(*(uint32_t*)&h01, *(uint32_t*)&h23);
            *(uint2*)(hrow + i4 * 4) = pk;
        }
#pragma unroll
        for (int off = 16; off; off >>= 1) s += __shfl_xor_sync(0xffffffffu, s, off);
        if (lane == 0) g_wsum[wrow] = s;
    } else {
        int i = (b - PREP_CONV_BLKS - PREP_W_BLKS) * 256 + threadIdx.x;
        float4 z = make_float4(0.f, 0.f, 0.f, 0.f);
        if (i == 0) g_ticket = 0u;
        if (i < 36864) {
            ((float4*)g_dot)[i] = z;
        } else if (i < 36864 + 8192) {
            ((float4*)&g_sum[1][0])[i - 36864] = z;
        } else if (i < 36864 + 8192 + 96) {
            ((uint4*)g_ready)[i - (36864 + 8192)] = make_uint4(0u, 0u, 0u, 0u);
        }
    }
}

// ---------------- persistent fused network ----------------
__global__ __launch_bounds__(256, 2)
void persist_net(const float* __restrict__ x,
                 const float* __restrict__ bias_all,
                 float* __restrict__ out_base)
{
    extern __shared__ __align__(128) char dsm[];
    uint32_t sb = s2u(dsm);
    float* wsum_s = (float*)(dsm + SMEM_MAIN);
    float* bias_s = (float*)(dsm + SMEM_MAIN + 512);
    float* c_s    = (float*)(dsm + SMEM_MAIN + 1024);
    uint32_t mbF = sb + SMEM_MAIN + 1536;     // 3 x 8B full barriers
    uint32_t mbE = mbF + 24;                  // 3 x 8B empty barriers
    int* it_s    = (int*)(dsm + SMEM_MAIN + 1600);

    int tid = threadIdx.x, warp = tid >> 5, lane = tid & 31;

    if (tid < 3)            MBAR_INIT(mbF + tid * 8, 256u);
    else if (tid < 6)       MBAR_INIT(mbE + (tid - 3) * 8, 8u);
    if (tid == 0) it_s[0] = (int)atomicAdd(&g_ticket, 1u);
    __syncthreads();

    int wm = (warp >> 2) * 64;
    int wn = (warp & 3) * 32;
    int l7 = lane & 7;
    int rb = (lane & 7) + ((lane >> 4) << 3);
    int ahc = lane >> 4;
    int bhc = (lane >> 3) & 1;
    int g = lane >> 2, t = lane & 3;

    int u = tid & 7, r = tid >> 3;
    uint32_t swz = (uint32_t)((u ^ (r & 7)) << 4);
    uint32_t sA0 = sb + (uint32_t)r * 128 + swz;
    uint32_t sB0 = sb + BM * 128 + (uint32_t)r * 128 + swz;
    uint32_t aRowA = sb + (uint32_t)(wm + (lane & 15)) * 128;
    uint32_t bRowA = sb + BM * 128 + (uint32_t)(wn + rb) * 128;

    uint32_t pst = 0;
    int stg = 0;
    int item = it_s[0];
    bool bpref = false;

#define PROD_WAIT(s) do {                                                  \
        if (pst & (8u << (s))) {                                           \
            MBAR_WAIT(mbE + (uint32_t)(s) * 8, (pst >> (s)) & 1u);         \
            pst ^= 1u << (s);                                              \
        } else pst |= 8u << (s);                                           \
    } while (0)
#define CONS_WAIT(s) do {                                                  \
        MBAR_WAIT(mbF + (uint32_t)(s) * 8, (pst >> (8 + (s))) & 1u);       \
        pst ^= 256u << (s);                                                \
    } while (0)
#define NEXTS(s) ((s) + 1 == 3 ? 0 : (s) + 1)

#define LOAD_A4(gb, kt, st)                                               \
        {                                                                 \
            uint32_t so = (uint32_t)(st) * STAGE_BYTES;                   \
            uint64_t go = (uint64_t)(kt) * 128;                           \
            cp16(sA0 + so,         (gb) + go);                            \
            cp16(sA0 + so + 4096,  (gb) + go + 32768);                    \
            cp16(sA0 + so + 8192,  (gb) + go + 65536);                    \
            cp16(sA0 + so + 12288, (gb) + go + 98304);                    \
        }
#define LOAD_B4(gb, kt, st)                                               \
        {                                                                 \
            uint32_t so = (uint32_t)(st) * STAGE_BYTES;                   \
            uint64_t go = (uint64_t)(kt) * 128;                           \
            cp16(sB0 + so,         (gb) + go);                            \
            cp16(sB0 + so + 4096,  (gb) + go + 32768);                    \
            cp16(sB0 + so + 8192,  (gb) + go + 65536);                    \
            cp16(sB0 + so + 12288, (gb) + go + 98304);                    \
        }

    while (item < NITEMS) {
        int layer = item >> 9;
        int ti    = item & 511;
        int rowb  = ti >> 2;
        int col   = ti & 3;
        int rowB  = rowb * BM, colB = col * BN;
        int write_ah = (layer < NLAYER - 1);
        int ndots = (layer < 3) ? (layer + 1) : 0;
        int dosum = (layer <= 1);

        const __half* Ah = g_ha[layer];
        __half*       Oh = g_ha[(layer < 3) ? (layer + 1) : 3];
        const __half* Wl = g_wh + (size_t)layer * D * D;
        float* out = out_base + layer * D;

        uint64_t gA = g2g(Ah + (size_t)(rowB + r) * D + u * 8);
        uint64_t gB = g2g(Wl + (size_t)(colB + r) * D + u * 8);

        int s0 = stg, s1 = NEXTS(stg);

        if (!bpref) {                       // first item only: B not prefetched
            PROD_WAIT(s0); LOAD_B4(gB, 0, s0);
            PROD_WAIT(s1); LOAD_B4(gB, 1, s1);
        }

        if (layer > 0) {
            if (tid == 0) {
                const unsigned* cp = &g_ready[layer - 1][rowb];
                unsigned v;
                while (true) {
                    asm volatile("ld.acquire.gpu.global.u32 %0, [%1];"
                                 : "=r"(v) : "l"(cp) : "memory");
                    if (v >= 4u) break;
                    __nanosleep(64);
                }
            }
        }
        __syncthreads();    // item boundary: releases spin; protects c_s reuse

        if (tid < 128) {
            wsum_s[tid] = g_wsum[layer * D + colB + tid];
            bias_s[tid] = bias_all[layer * D + colB + tid];
            float c = 0.f;
            if (layer > 0) {
                int row = rowB + tid;
#pragma unroll
                for (int j = 0; j < 3; j++)
                    if (j < layer)
                        c = c + g_dot[layer - 1][j][row] + c * g_sum[j][row];
            }
            c_s[tid] = c;
        }

        LOAD_A4(gA, 0, s0); CP_MBAR_ARRIVE(mbF + (uint32_t)s0 * 8);
        LOAD_A4(gA, 1, s1); CP_MBAR_ARRIVE(mbF + (uint32_t)s1 * 8);

        float acc[4][4][4];
#pragma unroll
        for (int i = 0; i < 4; i++)
#pragma unroll
            for (int j = 0; j < 4; j++)
#pragma unroll
                for (int k = 0; k < 4; k++) acc[i][j][k] = 0.f;

        int scur = s0;
        int spre = NEXTS(s1);
#pragma unroll 1
        for (int kt = 0; kt < NKT; kt++) {
            if (kt < NKT - 2) {
                PROD_WAIT(spre);
                LOAD_A4(gA, kt + 2, spre);
                LOAD_B4(gB, kt + 2, spre);
                CP_MBAR_ARRIVE(mbF + (uint32_t)spre * 8);
                spre = NEXTS(spre);
            }
            CONS_WAIT(scur);

            uint32_t so = (uint32_t)scur * STAGE_BYTES;
#pragma unroll
            for (int s16 = 0; s16 < 4; s16++) {
                uint32_t afr[4][4];
                uint32_t bfr[2][4];
                uint32_t ca = (uint32_t)(((2 * s16 + ahc) ^ l7) << 4);
                uint32_t cb = (uint32_t)(((2 * s16 + bhc) ^ l7) << 4);
#pragma unroll
                for (int mt = 0; mt < 4; mt++)
                    ldsm4(afr[mt][0], afr[mt][1], afr[mt][2], afr[mt][3],
                          aRowA + so + (uint32_t)mt * 2048 + ca);
#pragma unroll
                for (int nb = 0; nb < 2; nb++)
                    ldsm4(bfr[nb][0], bfr[nb][1], bfr[nb][2], bfr[nb][3],
                          bRowA + so + (uint32_t)nb * 2048 + cb);
#pragma unroll
                for (int mt = 0; mt < 4; mt++)
#pragma unroll
                    for (int nt = 0; nt < 4; nt++) {
                        uint32_t bpair[2] = { bfr[nt >> 1][(nt & 1) * 2],
                                              bfr[nt >> 1][(nt & 1) * 2 + 1] };
                        mma_f16(acc[mt][nt], afr[mt], bpair);
                    }
            }

            __syncwarp();
            if (lane == 0) MBAR_ARRIVE(mbE + (uint32_t)scur * 8);
            scur = NEXTS(scur);
        }
        stg = scur;

        // ---- acquire next ticket; prefetch its weights during epilogue ----
        if (tid == 0) it_s[0] = (int)atomicAdd(&g_ticket, 1u);
        __syncthreads();    // publishes it_s; orders c_s writes before epilogue reads
        int nitem = it_s[0];
        if (nitem < NITEMS) {
            int nlayer = nitem >> 9;
            int ncolB  = (nitem & 3) * BN;
            const __half* nWl = g_wh + (size_t)nlayer * D * D;
            uint64_t ngB = g2g(nWl + (size_t)(ncolB + r) * D + u * 8);
            int t0 = stg, t1 = NEXTS(stg);
            PROD_WAIT(t0); LOAD_B4(ngB, 0, t0);
            PROD_WAIT(t1); LOAD_B4(ngB, 1, t1);
            bpref = true;
        }

        // ---- epilogue ----
#pragma unroll
        for (int mt = 0; mt < 4; mt++) {
            int mloc = wm + mt * 16 + g;
            int m0 = rowB + mloc;
            float c0 = c_s[mloc];
            float c1 = c_s[mloc + 8];
            float* o0 = out + (size_t)m0 * OUTD + colB;
            float* o1 = o0 + (size_t)8 * OUTD;
            __half* h0 = Oh + (size_t)m0 * D + colB;
            __half* h1 = h0 + (size_t)8 * D;

            const __half* ph[3];
#pragma unroll
            for (int j = 0; j < 3; j++)
                ph[j] = g_ha[j] + (size_t)m0 * D + colB;

            float dac0[4] = {0.f, 0.f, 0.f, 0.f};
            float dac1[4] = {0.f, 0.f, 0.f, 0.f};

#pragma unroll
            for (int nt = 0; nt < 4; nt++) {
                int cc = wn + nt * 8 + 2 * t;
                float w0 = wsum_s[cc], w1 = wsum_s[cc + 1];
                float bb0 = bias_s[cc], bb1 = bias_s[cc + 1];
                float v00 = acc[mt][nt][0] + c0 * w0 + bb0;
                float v01 = acc[mt][nt][1] + c0 * w1 + bb1;
                float v10 = acc[mt][nt][2] + c1 * w0 + bb0;
                float v11 = acc[mt][nt][3] + c1 * w1 + bb1;
                *(float2*)(o0 + cc) = make_float2(v00, v01);
                *(float2*)(o1 + cc) = make_float2(v10, v11);
                if (write_ah) {
                    *(__half2*)(h0 + cc) = __floats2half2_rn(v00, v01);
                    *(__half2*)(h1 + cc) = __floats2half2_rn(v10, v11);
                }
#pragma unroll
                for (int j = 0; j < 3; j++)
                    if (j < ndots) {
                        float2 u0 = __half22float2(*(const __half2*)(ph[j] + cc));
                        float2 u1 = __half22float2(*(const __half2*)(ph[j] + 8 * D + cc));
                        dac0[j] += v00 * u0.x + v01 * u0.y;
                        dac1[j] += v10 * u1.x + v11 * u1.y;
                    }
                if (dosum) {
                    dac0[3] += v00 + v01;
                    dac1[3] += v10 + v11;
                }
            }

#pragma unroll
            for (int j = 0; j < 4; j++) {
                bool live = (j < ndots) || (j == 3 && dosum);
                if (!live) continue;
                float r0 = dac0[j], r1 = dac1[j];
                r0 += __shfl_xor_sync(0xffffffffu, r0, 1);
                r0 += __shfl_xor_sync(0xffffffffu, r0, 2);
                r1 += __shfl_xor_sync(0xffffffffu, r1, 1);
                r1 += __shfl_xor_sync(0xffffffffu, r1, 2);
                if (t == 0) {
                    if (j < 3) {
                        atomicAdd(&g_dot[layer][j][m0], r0);
                        atomicAdd(&g_dot[layer][j][m0 + 8], r1);
                    } else {
                        atomicAdd(&g_sum[layer + 1][m0], r0);
                        atomicAdd(&g_sum[layer + 1][m0 + 8], r1);
                    }
                }
            }
        }

        // ---- signal completion (only when there are consumers) ----
        if (layer < 3) {
            __threadfence();
            __syncthreads();
            if (tid == 0) {
                asm volatile("red.release.gpu.global.add.u32 [%0], %1;"
                             :: "l"(&g_ready[layer][rowb]), "r"(1u) : "memory");
            }
        }

        item = nitem;
    }
}

// ---------------------------------------------------------------------------
extern "C" void kernel_launch(void* const* d_in, const int* in_sizes, int n_in,
                              void* d_out, int out_size) {
    const float* x = (const float*)d_in[0];
    const float* W = (const float*)d_in[1];
    const float* b = (const float*)d_in[2];
    float* out = (float*)d_out;

    cudaFuncSetAttribute(persist_net, cudaFuncAttributeMaxDynamicSharedMemorySize, SMEM_TOTAL);

    int dev = 0, sms = 148;
    cudaGetDevice(&dev);
    cudaDeviceGetAttribute(&sms, cudaDevAttrMultiProcessorCount, dev);
    int grid = 2 * sms;
    if (grid > NITEMS) grid = NITEMS;

    prep_all<<<PREP_BLKS, 256>>>(x, W);
    persist_net<<<grid, 256, SMEM_TOTAL>>>(x, b, out);
}

// round 17
// speedup vs baseline: 1.0446x; 1.0446x over previous
#include <cuda_runtime.h>
#include <cuda_fp16.h>
#include <cstdint>

#define BATCH  16384
#define D      512
#define OUTD   2048
#define NLAYER 4

#define BM 128
#define BN 128
#define NKT 8                             // k-tiles of 64 halves
#define NROWB (BATCH / BM)                // 128
#define NITEMS (NLAYER * NROWB * 4)       // 2048
#define STAGE_BYTES (BM * 128 + BN * 128) // 32768
#define SMEM_MAIN (3 * STAGE_BYTES)       // 98304
#define SMEM_TOTAL (SMEM_MAIN + 2048)

__device__ __align__(16) float  g_wsum[NLAYER * D];
__device__ __align__(16) float  g_dot[3][3][BATCH];
__device__ __align__(16) float  g_sum[3][BATCH];
__device__ __align__(16) unsigned g_ready[3][NROWB];
__device__ __half g_ha[4][(size_t)BATCH * D];
__device__ __half g_wh[(size_t)NLAYER * D * D];

// ---------------- helpers ----------------
__device__ __forceinline__ uint32_t s2u(const void* p) {
    uint32_t a;
    asm("{ .reg .u64 t; cvta.to.shared.u64 t, %1; cvt.u32.u64 %0, t; }" : "=r"(a) : "l"(p));
    return a;
}
__device__ __forceinline__ uint64_t g2g(const void* p) {
    uint64_t a;
    asm("cvta.to.global.u64 %0, %1;" : "=l"(a) : "l"(p));
    return a;
}
__device__ __forceinline__ void cp16(uint32_t s, uint64_t g) {
    asm volatile("cp.async.cg.shared.global [%0], [%1], 16;" :: "r"(s), "l"(g) : "memory");
}
__device__ __forceinline__ void stg_cs_f2(float* p, float a, float b) {
    asm volatile("st.global.cs.v2.f32 [%0], {%1, %2};" :: "l"(p), "f"(a), "f"(b) : "memory");
}
#define MBAR_INIT(a, n) asm volatile("mbarrier.init.shared.b64 [%0], %1;" :: "r"(a), "r"(n) : "memory")
#define MBAR_ARRIVE(a)  asm volatile("mbarrier.arrive.shared.b64 _, [%0];" :: "r"(a) : "memory")
#define CP_MBAR_ARRIVE(a) \
    asm volatile("cp.async.mbarrier.arrive.noinc.shared.b64 [%0];" :: "r"(a) : "memory")
#define MBAR_WAIT(a, par) do {                                                        \
    uint32_t _m = (a), _p = (par), _d;                                                \
    asm volatile("{ .reg .pred p; mbarrier.try_wait.parity.acquire.cta.shared::cta.b64 p, [%1], %2; selp.b32 %0,1,0,p; }" \
                 : "=r"(_d) : "r"(_m), "r"(_p) : "memory");                           \
    if (!_d) {                                                                        \
        asm volatile("{ .reg .pred P1; WL_%=: mbarrier.try_wait.parity.acquire.cta.shared::cta.b64 P1, [%0], %1, 0x989680; @P1 bra.uni WD_%=; bra.uni WL_%=; WD_%=: }" \
                     :: "r"(_m), "r"(_p) : "memory");                                 \
    } } while (0)

__device__ __forceinline__ void ldsm4(uint32_t& r0, uint32_t& r1, uint32_t& r2, uint32_t& r3,
                                      uint32_t addr) {
    asm volatile("ldmatrix.sync.aligned.m8n8.x4.shared.b16 {%0,%1,%2,%3}, [%4];"
                 : "=r"(r0), "=r"(r1), "=r"(r2), "=r"(r3) : "r"(addr));
}
__device__ __forceinline__ void mma_f16(float* c, const uint32_t* a, const uint32_t* b) {
    asm volatile(
        "mma.sync.aligned.m16n8k16.row.col.f32.f16.f16.f32 "
        "{%0,%1,%2,%3}, {%4,%5,%6,%7}, {%8,%9}, {%0,%1,%2,%3};\n"
        : "+f"(c[0]), "+f"(c[1]), "+f"(c[2]), "+f"(c[3])
        : "r"(a[0]), "r"(a[1]), "r"(a[2]), "r"(a[3]), "r"(b[0]), "r"(b[1]));
}

// ---------------- fused prep ----------------
#define PREP_CONV_BLKS 2048
#define PREP_W_BLKS    256
#define PREP_ZERO_BLKS 180
#define PREP_BLKS (PREP_CONV_BLKS + PREP_W_BLKS + PREP_ZERO_BLKS)

__global__ void prep_all(const float* __restrict__ x, const float* __restrict__ W) {
    int b = blockIdx.x;
    int warp = threadIdx.x >> 5, lane = threadIdx.x & 31;

    if (b < PREP_CONV_BLKS) {
        int row = b * 8 + warp;
        const float4* rp = (const float4*)(x + (size_t)row * D);
        __half* hp = g_ha[0] + (size_t)row * D;
        float s = 0.f;
#pragma unroll
        for (int k = 0; k < 4; k++) {
            int i4 = lane + 32 * k;
            float4 v = rp[i4];
            s += v.x + v.y + v.z + v.w;
            __half2 h01 = __floats2half2_rn(v.x, v.y);
            __half2 h23 = __floats2half2_rn(v.z, v.w);
            uint2 pk = make_uint2(*(uint32_t*)&h01, *(uint32_t*)&h23);
            *(uint2*)(hp + i4 * 4) = pk;
        }
#pragma unroll
        for (int off = 16; off; off >>= 1) s += __shfl_xor_sync(0xffffffffu, s, off);
        if (lane == 0) g_sum[0][row] = s;
    } else if (b < PREP_CONV_BLKS + PREP_W_BLKS) {
        int wrow = (b - PREP_CONV_BLKS) * 8 + warp;
        const float4* row = (const float4*)(W + (size_t)wrow * D);
        __half* hrow = g_wh + (size_t)wrow * D;
        float s = 0.f;
#pragma unroll
        for (int k = 0; k < 4; k++) {
            int i4 = lane + 32 * k;
            float4 v = row[i4];
            s += v.x + v.y + v.z + v.w;
            __half2 h01 = __floats2half2_rn(v.x, v.y);
            __half2 h23 = __floats2half2_rn(v.z, v.w);
            uint2 pk = make_uint2(*(uint32_t*)&h01, *(uint32_t*)&h23);
            *(uint2*)(hrow + i4 * 4) = pk;
        }
#pragma unroll
        for (int off = 16; off; off >>= 1) s += __shfl_xor_sync(0xffffffffu, s, off);
        if (lane == 0) g_wsum[wrow] = s;
    } else {
        int i = (b - PREP_CONV_BLKS - PREP_W_BLKS) * 256 + threadIdx.x;
        float4 z = make_float4(0.f, 0.f, 0.f, 0.f);
        if (i < 36864) {
            ((float4*)g_dot)[i] = z;
        } else if (i < 36864 + 8192) {
            ((float4*)&g_sum[1][0])[i - 36864] = z;
        } else if (i < 36864 + 8192 + 96) {
            ((uint4*)g_ready)[i - (36864 + 8192)] = make_uint4(0u, 0u, 0u, 0u);
        }
    }
}

// ---------------- persistent fused network (mbarrier pipeline) --------------
__global__ __launch_bounds__(256, 2)
void persist_net(const float* __restrict__ x,
                 const float* __restrict__ bias_all,
                 float* __restrict__ out_base)
{
    extern __shared__ __align__(128) char dsm[];
    uint32_t sb = s2u(dsm);
    float* wsum_s = (float*)(dsm + SMEM_MAIN);
    float* bias_s = (float*)(dsm + SMEM_MAIN + 512);
    float* c_s    = (float*)(dsm + SMEM_MAIN + 1024);
    uint32_t mbF = sb + SMEM_MAIN + 1536;     // 3 x 8B full barriers
    uint32_t mbE = mbF + 24;                  // 3 x 8B empty barriers

    int tid = threadIdx.x, warp = tid >> 5, lane = tid & 31;

    if (tid < 3)            MBAR_INIT(mbF + tid * 8, 256u);
    else if (tid < 6)       MBAR_INIT(mbE + (tid - 3) * 8, 8u);
    __syncthreads();

    int wm = (warp >> 2) * 64;
    int wn = (warp & 3) * 32;
    int l7 = lane & 7;
    int rb = (lane & 7) + ((lane >> 4) << 3);
    int ahc = lane >> 4;
    int bhc = (lane >> 3) & 1;
    int g = lane >> 2, t = lane & 3;

    int u = tid & 7, r = tid >> 3;
    uint32_t swz = (uint32_t)((u ^ (r & 7)) << 4);
    uint32_t sA0 = sb + (uint32_t)r * 128 + swz;
    uint32_t sB0 = sb + BM * 128 + (uint32_t)r * 128 + swz;
    uint32_t aRowA = sb + (uint32_t)(wm + (lane & 15)) * 128;
    uint32_t bRowA = sb + BM * 128 + (uint32_t)(wn + rb) * 128;

    uint32_t pst = 0;
    int stg = 0;

#define PROD_WAIT(s) do {                                                  \
        if (pst & (8u << (s))) {                                           \
            MBAR_WAIT(mbE + (uint32_t)(s) * 8, (pst >> (s)) & 1u);         \
            pst ^= 1u << (s);                                              \
        } else pst |= 8u << (s);                                           \
    } while (0)
#define CONS_WAIT(s) do {                                                  \
        MBAR_WAIT(mbF + (uint32_t)(s) * 8, (pst >> (8 + (s))) & 1u);       \
        pst ^= 256u << (s);                                                \
    } while (0)
#define NEXTS(s) ((s) + 1 == 3 ? 0 : (s) + 1)

    for (int item = blockIdx.x; item < NITEMS; item += gridDim.x) {
        int layer = item >> 9;
        int ti    = item & 511;
        int rowb  = ti >> 2;
        int col   = ti & 3;
        int rowB  = rowb * BM, colB = col * BN;
        int write_ah = (layer < NLAYER - 1);
        int ndots = (layer < 3) ? (layer + 1) : 0;
        int dosum = (layer <= 1);

        const __half* Ah = g_ha[layer];
        __half*       Oh = g_ha[(layer < 3) ? (layer + 1) : 3];
        const __half* Wl = g_wh + (size_t)layer * D * D;
        float* out = out_base + layer * D;

        uint64_t gA = g2g(Ah + (size_t)(rowB + r) * D + u * 8);
        uint64_t gB = g2g(Wl + (size_t)(colB + r) * D + u * 8);

#define LOAD_A(kt, st)                                                    \
        {                                                                 \
            uint32_t so = (uint32_t)(st) * STAGE_BYTES;                   \
            uint64_t go = (uint64_t)(kt) * 128;                           \
            cp16(sA0 + so,         gA + go);                              \
            cp16(sA0 + so + 4096,  gA + go + 32768);                      \
            cp16(sA0 + so + 8192,  gA + go + 65536);                      \
            cp16(sA0 + so + 12288, gA + go + 98304);                      \
        }
#define LOAD_B(kt, st)                                                    \
        {                                                                 \
            uint32_t so = (uint32_t)(st) * STAGE_BYTES;                   \
            uint64_t go = (uint64_t)(kt) * 128;                           \
            cp16(sB0 + so,         gB + go);                              \
            cp16(sB0 + so + 4096,  gB + go + 32768);                      \
            cp16(sB0 + so + 8192,  gB + go + 65536);                      \
            cp16(sB0 + so + 12288, gB + go + 98304);                      \
        }

        int s0 = stg, s1 = NEXTS(stg);

        // producer waits + B prefetch (weights independent of producers)
        PROD_WAIT(s0); LOAD_B(0, s0);
        PROD_WAIT(s1); LOAD_B(1, s1);

        if (layer > 0) {
            if (tid == 0) {
                const unsigned* cp = &g_ready[layer - 1][rowb];
                unsigned v;
                while (true) {
                    asm volatile("ld.acquire.gpu.global.u32 %0, [%1];"
                                 : "=r"(v) : "l"(cp) : "memory");
                    if (v >= 4u) break;
                    __nanosleep(64);
                }
            }
        }
        __syncthreads();    // item boundary: releases spin; protects c_s/wsum/bias reuse

        if (tid < 128) {
            wsum_s[tid] = g_wsum[layer * D + colB + tid];
            bias_s[tid] = bias_all[layer * D + colB + tid];
            float c = 0.f;
            if (layer > 0) {
                int row = rowB + tid;
#pragma unroll
                for (int j = 0; j < 3; j++)
                    if (j < layer)
                        c = c + g_dot[layer - 1][j][row] + c * g_sum[j][row];
            }
            c_s[tid] = c;
        }

        LOAD_A(0, s0); CP_MBAR_ARRIVE(mbF + (uint32_t)s0 * 8);
        LOAD_A(1, s1); CP_MBAR_ARRIVE(mbF + (uint32_t)s1 * 8);

        float acc[4][4][4];
#pragma unroll
        for (int i = 0; i < 4; i++)
#pragma unroll
            for (int j = 0; j < 4; j++)
#pragma unroll
                for (int k = 0; k < 4; k++) acc[i][j][k] = 0.f;

        int scur = s0;
        int spre = NEXTS(s1);
#pragma unroll 1
        for (int kt = 0; kt < NKT; kt++) {
            if (kt < NKT - 2) {
                PROD_WAIT(spre);
                LOAD_A(kt + 2, spre);
                LOAD_B(kt + 2, spre);
                CP_MBAR_ARRIVE(mbF + (uint32_t)spre * 8);
                spre = NEXTS(spre);
            }
            CONS_WAIT(scur);

            uint32_t so = (uint32_t)scur * STAGE_BYTES;
#pragma unroll
            for (int s16 = 0; s16 < 4; s16++) {
                uint32_t afr[4][4];
                uint32_t bfr[2][4];
                uint32_t ca = (uint32_t)(((2 * s16 + ahc) ^ l7) << 4);
                uint32_t cb = (uint32_t)(((2 * s16 + bhc) ^ l7) << 4);
#pragma unroll
                for (int mt = 0; mt < 4; mt++)
                    ldsm4(afr[mt][0], afr[mt][1], afr[mt][2], afr[mt][3],
                          aRowA + so + (uint32_t)mt * 2048 + ca);
#pragma unroll
                for (int nb = 0; nb < 2; nb++)
                    ldsm4(bfr[nb][0], bfr[nb][1], bfr[nb][2], bfr[nb][3],
                          bRowA + so + (uint32_t)nb * 2048 + cb);
#pragma unroll
                for (int mt = 0; mt < 4; mt++)
#pragma unroll
                    for (int nt = 0; nt < 4; nt++) {
                        uint32_t bpair[2] = { bfr[nt >> 1][(nt & 1) * 2],
                                              bfr[nt >> 1][(nt & 1) * 2 + 1] };
                        mma_f16(acc[mt][nt], afr[mt], bpair);
                    }
            }

            __syncwarp();
            if (lane == 0) MBAR_ARRIVE(mbE + (uint32_t)scur * 8);
            scur = NEXTS(scur);
        }
        stg = scur;   // advanced by 8 tiles (mod 3)

        __syncthreads();    // c_s/wsum/bias fully written before epilogue reads

        // ---- epilogue ----
#pragma unroll
        for (int mt = 0; mt < 4; mt++) {
            int mloc = wm + mt * 16 + g;
            int m0 = rowB + mloc;
            float c0 = c_s[mloc];
            float c1 = c_s[mloc + 8];
            float* o0 = out + (size_t)m0 * OUTD + colB;
            float* o1 = o0 + (size_t)8 * OUTD;
            __half* h0 = Oh + (size_t)m0 * D + colB;
            __half* h1 = h0 + (size_t)8 * D;

            const __half* ph[3];
#pragma unroll
            for (int j = 0; j < 3; j++)
                ph[j] = g_ha[j] + (size_t)m0 * D + colB;

            float dac0[4] = {0.f, 0.f, 0.f, 0.f};
            float dac1[4] = {0.f, 0.f, 0.f, 0.f};

#pragma unroll
            for (int nt = 0; nt < 4; nt++) {
                int cc = wn + nt * 8 + 2 * t;
                float w0 = wsum_s[cc], w1 = wsum_s[cc + 1];
                float bb0 = bias_s[cc], bb1 = bias_s[cc + 1];
                float v00 = acc[mt][nt][0] + c0 * w0 + bb0;
                float v01 = acc[mt][nt][1] + c0 * w1 + bb1;
                float v10 = acc[mt][nt][2] + c1 * w0 + bb0;
                float v11 = acc[mt][nt][3] + c1 * w1 + bb1;
                stg_cs_f2(o0 + cc, v00, v01);
                stg_cs_f2(o1 + cc, v10, v11);
                if (write_ah) {
                    *(__half2*)(h0 + cc) = __floats2half2_rn(v00, v01);
                    *(__half2*)(h1 + cc) = __floats2half2_rn(v10, v11);
                }
#pragma unroll
                for (int j = 0; j < 3; j++)
                    if (j < ndots) {
                        float2 u0 = __half22float2(*(const __half2*)(ph[j] + cc));
                        float2 u1 = __half22float2(*(const __half2*)(ph[j] + 8 * D + cc));
                        dac0[j] += v00 * u0.x + v01 * u0.y;
                        dac1[j] += v10 * u1.x + v11 * u1.y;
                    }
                if (dosum) {
                    dac0[3] += v00 + v01;
                    dac1[3] += v10 + v11;
                }
            }

#pragma unroll
            for (int j = 0; j < 4; j++) {
                bool live = (j < ndots) || (j == 3 && dosum);
                if (!live) continue;
                float r0 = dac0[j], r1 = dac1[j];
                r0 += __shfl_xor_sync(0xffffffffu, r0, 1);
                r0 += __shfl_xor_sync(0xffffffffu, r0, 2);
                r1 += __shfl_xor_sync(0xffffffffu, r1, 1);
                r1 += __shfl_xor_sync(0xffffffffu, r1, 2);
                if (t == 0) {
                    if (j < 3) {
                        atomicAdd(&g_dot[layer][j][m0], r0);
                        atomicAdd(&g_dot[layer][j][m0 + 8], r1);
                    } else {
                        atomicAdd(&g_sum[layer + 1][m0], r0);
                        atomicAdd(&g_sum[layer + 1][m0 + 8], r1);
                    }
                }
            }
        }

        // ---- signal completion (only when there are consumers) ----
        if (layer < 3) {
            __threadfence();
            __syncthreads();
            if (tid == 0) {
                asm volatile("red.release.gpu.global.add.u32 [%0], %1;"
                             :: "l"(&g_ready[layer][rowb]), "r"(1u) : "memory");
            }
        }
    }
}

// ---------------------------------------------------------------------------
extern "C" void kernel_launch(void* const* d_in, const int* in_sizes, int n_in,
                              void* d_out, int out_size) {
    const float* x = (const float*)d_in[0];
    const float* W = (const float*)d_in[1];
    const float* b = (const float*)d_in[2];
    float* out = (float*)d_out;

    cudaFuncSetAttribute(persist_net, cudaFuncAttributeMaxDynamicSharedMemorySize, SMEM_TOTAL);

    int dev = 0, sms = 148;
    cudaGetDevice(&dev);
    cudaDeviceGetAttribute(&sms, cudaDevAttrMultiProcessorCount, dev);
    int grid = 2 * sms;
    if (grid > NITEMS) grid = NITEMS;

    prep_all<<<PREP_BLKS, 256>>>(x, W);
    persist_net<<<grid, 256, SMEM_TOTAL>>>(x, b, out);
}